// round 2
// baseline (speedup 1.0000x reference)
#include <cuda_runtime.h>

#define TT  128
#define BB  1024
#define DIN 128
#define HH  256
#define G3  768   // 3*H, gate-interleaved columns

// ---------------- device scratch (static globals; no allocations) ----------
__device__ float g_Wx0p[G3 * DIN];
__device__ float g_Wh0p[G3 * HH];
__device__ float g_Wx1p[G3 * HH];
__device__ float g_Wh1p[G3 * HH];
__device__ float g_bx0p[G3];
__device__ float g_bh0p[G3];
__device__ float g_bx1p[G3];
__device__ float g_bh1p[G3];
__device__ float g_xg[(size_t)TT * BB * G3];    // 402 MB: precomputed x-gates
__device__ float g_out0[(size_t)TT * BB * HH];  // 134 MB: layer-0 outputs
__device__ float g_hbuf[2][BB * HH];            // double-buffered hidden state
__device__ int            g_cnt;
__device__ volatile int   g_gen;

// ---------------- helpers --------------------------------------------------
__device__ __forceinline__ float sigm_f(float x) {
    return __fdividef(1.0f, 1.0f + __expf(-x));
}
__device__ __forceinline__ float tanh_f(float x) {
    x = fminf(fmaxf(x, -15.0f), 15.0f);
    float e = __expf(-2.0f * x);
    return __fdividef(1.0f - e, 1.0f + e);
}

// software grid barrier (all CTAs resident; generation counter survives replays)
__device__ __forceinline__ void grid_sync(int nblocks) {
    __syncthreads();
    if (threadIdx.x == 0) {
        __threadfence();
        int gen = g_gen;
        if (atomicAdd(&g_cnt, 1) == nblocks - 1) {
            g_cnt = 0;
            __threadfence();
            g_gen = gen + 1;
        } else {
            while (g_gen == gen) { __nanosleep(32); }
            __threadfence();
        }
    }
    __syncthreads();
}

// ---------------- weight reordering: W'[3j+g] = W[g*H + j] -----------------
__global__ void reorder_kernel(const float* __restrict__ Wx0, const float* __restrict__ bx0,
                               const float* __restrict__ Wh0, const float* __restrict__ bh0,
                               const float* __restrict__ Wx1, const float* __restrict__ bx1,
                               const float* __restrict__ Wh1, const float* __restrict__ bh1) {
    int tid = blockIdx.x * blockDim.x + threadIdx.x;
    int stride = gridDim.x * blockDim.x;
    for (int idx = tid; idx < G3 * DIN; idx += stride) {
        int n = idx / DIN, k = idx % DIN;
        int j = n / 3, g = n % 3;
        g_Wx0p[idx] = Wx0[(g * HH + j) * DIN + k];
    }
    for (int idx = tid; idx < G3 * HH; idx += stride) {
        int n = idx / HH, k = idx % HH;
        int j = n / 3, g = n % 3;
        int s = (g * HH + j) * HH + k;
        g_Wh0p[idx] = Wh0[s];
        g_Wx1p[idx] = Wx1[s];
        g_Wh1p[idx] = Wh1[s];
    }
    for (int idx = tid; idx < G3; idx += stride) {
        int j = idx / 3, g = idx % 3;
        g_bx0p[idx] = bx0[g * HH + j];
        g_bh0p[idx] = bh0[g * HH + j];
        g_bx1p[idx] = bx1[g * HH + j];
        g_bh1p[idx] = bh1[g * HH + j];
    }
}

// ---------------- big GEMM: C[M,768] = X[M,K] @ W'[768,K]^T + b' -----------
// Tile 128x128, 256 threads, 8x8 register tile, KC=16, register prefetch.
__global__ __launch_bounds__(256) void xgates_kernel(const float* __restrict__ X,
                                                     const float* __restrict__ Wp,
                                                     const float* __restrict__ bp,
                                                     float* __restrict__ C, int K) {
    __shared__ float As[16 * 128];
    __shared__ float Bs[16 * 128];
    const int tid = threadIdx.x;
    const int tx = tid & 15, ty = tid >> 4;
    const int m0 = blockIdx.y * 128;
    const int n0 = blockIdx.x * 128;

    const int rowL = tid >> 2;          // 0..63 (+64 for p=1)
    const int kqL  = (tid & 3) * 4;     // 0,4,8,12

    float acc[8][8];
#pragma unroll
    for (int i = 0; i < 8; i++)
#pragma unroll
        for (int j = 0; j < 8; j++) acc[i][j] = 0.0f;

    float4 pa[2], pb[2];
#pragma unroll
    for (int p = 0; p < 2; p++) {
        int row = rowL + p * 64;
        pa[p] = *(const float4*)&X [(size_t)(m0 + row) * K + kqL];
        pb[p] = *(const float4*)&Wp[(size_t)(n0 + row) * K + kqL];
    }

    for (int kc = 0; kc < K; kc += 16) {
        __syncthreads();
#pragma unroll
        for (int p = 0; p < 2; p++) {
            int row = rowL + p * 64;
            As[(kqL + 0) * 128 + row] = pa[p].x;
            As[(kqL + 1) * 128 + row] = pa[p].y;
            As[(kqL + 2) * 128 + row] = pa[p].z;
            As[(kqL + 3) * 128 + row] = pa[p].w;
            Bs[(kqL + 0) * 128 + row] = pb[p].x;
            Bs[(kqL + 1) * 128 + row] = pb[p].y;
            Bs[(kqL + 2) * 128 + row] = pb[p].z;
            Bs[(kqL + 3) * 128 + row] = pb[p].w;
        }
        __syncthreads();
        int kn = kc + 16;
        if (kn < K) {
#pragma unroll
            for (int p = 0; p < 2; p++) {
                int row = rowL + p * 64;
                pa[p] = *(const float4*)&X [(size_t)(m0 + row) * K + kn + kqL];
                pb[p] = *(const float4*)&Wp[(size_t)(n0 + row) * K + kn + kqL];
            }
        }
#pragma unroll
        for (int k = 0; k < 16; k++) {
            float4 a0 = *(const float4*)&As[k * 128 + ty * 8];
            float4 a1 = *(const float4*)&As[k * 128 + ty * 8 + 4];
            float4 b0 = *(const float4*)&Bs[k * 128 + tx * 8];
            float4 b1 = *(const float4*)&Bs[k * 128 + tx * 8 + 4];
            float a[8] = {a0.x, a0.y, a0.z, a0.w, a1.x, a1.y, a1.z, a1.w};
            float b[8] = {b0.x, b0.y, b0.z, b0.w, b1.x, b1.y, b1.z, b1.w};
#pragma unroll
            for (int i = 0; i < 8; i++)
#pragma unroll
                for (int j = 0; j < 8; j++)
                    acc[i][j] = fmaf(a[i], b[j], acc[i][j]);
        }
    }

    float bb[8];
#pragma unroll
    for (int j = 0; j < 8; j++) bb[j] = bp[n0 + tx * 8 + j];
#pragma unroll
    for (int i = 0; i < 8; i++) {
        int m = m0 + ty * 8 + i;
        float4 o0 = make_float4(acc[i][0] + bb[0], acc[i][1] + bb[1],
                                acc[i][2] + bb[2], acc[i][3] + bb[3]);
        float4 o1 = make_float4(acc[i][4] + bb[4], acc[i][5] + bb[5],
                                acc[i][6] + bb[6], acc[i][7] + bb[7]);
        float* cp = &C[(size_t)m * G3 + n0 + tx * 8];
        *(float4*)cp = o0;
        *(float4*)(cp + 4) = o1;
    }
}

// ---------------- persistent recurrent kernel ------------------------------
// Grid 8x16 = 128 CTAs (all resident), 256 threads, Wh' tile (256x96) smem-resident.
// Tile: 64 batch rows x 96 interleaved gate cols (= 32 hidden cols, all 3 gates).
#define WHS_STRIDE 98
#define SMEM_REC ((256 * WHS_STRIDE + 32 * 64) * 4)

__global__ __launch_bounds__(256) void recurrent_kernel(
    const float* __restrict__ xg, const float* __restrict__ Whp,
    const float* __restrict__ bhp, const float* __restrict__ h0,
    const float* __restrict__ gamma, const float* __restrict__ beta,
    float* __restrict__ out_seq, float* __restrict__ final_h, int nblocks) {
    extern __shared__ float smem[];
    float* Whs = smem;                       // [256][98] (padded)
    float* As  = smem + 256 * WHS_STRIDE;    // [32][64] transposed h chunk

    const int tid = threadIdx.x;
    const int tx = tid & 15, ty = tid >> 4;
    const int n0 = blockIdx.x * 96;          // gate-col base (interleaved)
    const int b0 = blockIdx.y * 64;          // batch base
    const int c0 = 6 * tx;
    const int j0 = n0 / 3 + 2 * tx;          // hidden col base (2 per thread), even

    // stage Wh' tile: Whs[k][c] = Wh'[n0+c][k]
    for (int idx = tid; idx < 96 * 64; idx += 256) {
        int c = idx >> 6;
        int kq = (idx & 63) * 4;
        float4 v = *(const float4*)&Whp[(size_t)(n0 + c) * HH + kq];
        Whs[(kq + 0) * WHS_STRIDE + c] = v.x;
        Whs[(kq + 1) * WHS_STRIDE + c] = v.y;
        Whs[(kq + 2) * WHS_STRIDE + c] = v.z;
        Whs[(kq + 3) * WHS_STRIDE + c] = v.w;
    }

    float bias[6];
#pragma unroll
    for (int v = 0; v < 6; v++) bias[v] = bhp[n0 + c0 + v];

    float gm[4][2], bt[4][2];
#pragma unroll
    for (int i = 0; i < 4; i++) {
        int b = b0 + ty * 4 + i;
#pragma unroll
        for (int u = 0; u < 2; u++) {
            gm[i][u] = gamma[b * HH + j0 + u];
            bt[i][u] = beta [b * HH + j0 + u];
        }
    }

    // init hidden state (each block covers its 64 rows x 32 hidden cols)
    {
        int jb = n0 / 3;
        for (int idx = tid; idx < 64 * 32; idx += 256) {
            int rr = idx >> 5, cc = idx & 31;
            int off = (b0 + rr) * HH + jb + cc;
            g_hbuf[0][off] = h0[off];
        }
    }
    grid_sync(nblocks);

    for (int t = 0; t < TT; t++) {
        const float* hcur = g_hbuf[t & 1];
        float* hnext = g_hbuf[(t + 1) & 1];

        float acc[4][6];
#pragma unroll
        for (int i = 0; i < 4; i++)
#pragma unroll
            for (int v = 0; v < 6; v++) acc[i][v] = bias[v];

        // prefetch chunk 0 (ld.cv: must bypass L1 — other SMs wrote h last step)
        float4 pre[2];
#pragma unroll
        for (int p = 0; p < 2; p++) {
            int i = tid + p * 256;
            int rr = i >> 3, kq = (i & 7) * 4;
            pre[p] = __ldcv((const float4*)&hcur[(size_t)(b0 + rr) * HH + kq]);
        }

        for (int kc = 0; kc < HH; kc += 32) {
            __syncthreads();
#pragma unroll
            for (int p = 0; p < 2; p++) {
                int i = tid + p * 256;
                int rr = i >> 3, kq = (i & 7) * 4;
                As[(kq + 0) * 64 + rr] = pre[p].x;
                As[(kq + 1) * 64 + rr] = pre[p].y;
                As[(kq + 2) * 64 + rr] = pre[p].z;
                As[(kq + 3) * 64 + rr] = pre[p].w;
            }
            __syncthreads();
            if (kc + 32 < HH) {
#pragma unroll
                for (int p = 0; p < 2; p++) {
                    int i = tid + p * 256;
                    int rr = i >> 3, kq = (i & 7) * 4;
                    pre[p] = __ldcv((const float4*)&hcur[(size_t)(b0 + rr) * HH + kc + 32 + kq]);
                }
            }
            const float* Wk = Whs + (size_t)kc * WHS_STRIDE + c0;
#pragma unroll
            for (int k = 0; k < 32; k++) {
                float4 av = *(const float4*)&As[k * 64 + ty * 4];
                const float2* wr2 = (const float2*)(Wk + k * WHS_STRIDE);
                float2 w01 = wr2[0], w23 = wr2[1], w45 = wr2[2];
                float a[4] = {av.x, av.y, av.z, av.w};
                float w[6] = {w01.x, w01.y, w23.x, w23.y, w45.x, w45.y};
#pragma unroll
                for (int i = 0; i < 4; i++)
#pragma unroll
                    for (int v = 0; v < 6; v++)
                        acc[i][v] = fmaf(a[i], w[v], acc[i][v]);
            }
        }

        // gates + FiLM + writes
#pragma unroll
        for (int i = 0; i < 4; i++) {
            int b = b0 + ty * 4 + i;
            const float* xgp = xg + ((size_t)t * BB + b) * G3 + n0 + c0;
            float hv[2];
#pragma unroll
            for (int u = 0; u < 2; u++) {
                float z  = sigm_f(xgp[3 * u + 0] + acc[i][3 * u + 0]);
                float r  = sigm_f(xgp[3 * u + 1] + acc[i][3 * u + 1]);
                float nn = tanh_f(xgp[3 * u + 2] + r * acc[i][3 * u + 2]);
                float hp = __ldcv(&hcur[(size_t)b * HH + j0 + u]);
                float h  = nn + z * (hp - nn);       // (1-z)*n + z*h
                hv[u] = fmaf(gm[i][u], h, bt[i][u]); // FiLM
            }
            float2 hv2 = make_float2(hv[0], hv[1]);
            *(float2*)&hnext[(size_t)b * HH + j0] = hv2;
            *(float2*)&out_seq[((size_t)t * BB + b) * HH + j0] = hv2;
            if (t == TT - 1)
                *(float2*)&final_h[(size_t)b * HH + j0] = hv2;
        }
        grid_sync(nblocks);
    }
}

// ---------------- host launcher -------------------------------------------
extern "C" void kernel_launch(void* const* d_in, const int* in_sizes, int n_in,
                              void* d_out, int out_size) {
    (void)in_sizes; (void)n_in; (void)out_size;
    const float* x      = (const float*)d_in[0];
    const float* init_s = (const float*)d_in[1];
    const float* gammas = (const float*)d_in[2];
    const float* betas  = (const float*)d_in[3];
    const float* Wx0 = (const float*)d_in[4];
    const float* bx0 = (const float*)d_in[5];
    const float* Wh0 = (const float*)d_in[6];
    const float* bh0 = (const float*)d_in[7];
    const float* Wx1 = (const float*)d_in[8];
    const float* bx1 = (const float*)d_in[9];
    const float* Wh1 = (const float*)d_in[10];
    const float* bh1 = (const float*)d_in[11];
    float* out = (float*)d_out;

    float *pWx0p, *pWh0p, *pWx1p, *pWh1p, *pbx0p, *pbh0p, *pbx1p, *pbh1p, *pxg, *pout0;
    cudaGetSymbolAddress((void**)&pWx0p, g_Wx0p);
    cudaGetSymbolAddress((void**)&pWh0p, g_Wh0p);
    cudaGetSymbolAddress((void**)&pWx1p, g_Wx1p);
    cudaGetSymbolAddress((void**)&pWh1p, g_Wh1p);
    cudaGetSymbolAddress((void**)&pbx0p, g_bx0p);
    cudaGetSymbolAddress((void**)&pbh0p, g_bh0p);
    cudaGetSymbolAddress((void**)&pbx1p, g_bx1p);
    cudaGetSymbolAddress((void**)&pbh1p, g_bh1p);
    cudaGetSymbolAddress((void**)&pxg,   g_xg);
    cudaGetSymbolAddress((void**)&pout0, g_out0);

    cudaFuncSetAttribute(recurrent_kernel,
                         cudaFuncAttributeMaxDynamicSharedMemorySize, SMEM_REC);

    const size_t out1_elems = (size_t)TT * BB * HH;

    reorder_kernel<<<768, 256>>>(Wx0, bx0, Wh0, bh0, Wx1, bx1, Wh1, bh1);

    // layer 0
    xgates_kernel<<<dim3(G3 / 128, (TT * BB) / 128), 256>>>(x, pWx0p, pbx0p, pxg, DIN);
    recurrent_kernel<<<dim3(8, 16), 256, SMEM_REC>>>(
        pxg, pWh0p, pbh0p, init_s, gammas, betas,
        pout0, out + out1_elems, 128);

    // layer 1
    xgates_kernel<<<dim3(G3 / 128, (TT * BB) / 128), 256>>>(pout0, pWx1p, pbx1p, pxg, HH);
    recurrent_kernel<<<dim3(8, 16), 256, SMEM_REC>>>(
        pxg, pWh1p, pbh1p, init_s + BB * HH, gammas + (size_t)BB * HH, betas + (size_t)BB * HH,
        out, out + out1_elems + (size_t)BB * HH, 128);
}

// round 6
// speedup vs baseline: 1.1683x; 1.1683x over previous
#include <cuda_runtime.h>
#include <cstdint>

#define TT  128
#define BB  1024
#define DIN 128
#define HH  256
#define G3  768   // 3*H, gate-interleaved columns

// ---------------- device scratch (static globals; no allocations) ----------
__device__ __align__(16) uint32_t g_Wx0t[G3 * DIN];  // tf32 bits, [col][k]
__device__ __align__(16) uint32_t g_Wx1t[G3 * HH];
__device__ __align__(16) float g_Wh0p[G3 * HH];
__device__ __align__(16) float g_Wh1p[G3 * HH];
__device__ float g_bx0p[G3];
__device__ float g_bh0p[G3];
__device__ float g_bx1p[G3];
__device__ float g_bh1p[G3];
__device__ __align__(16) float g_xg[(size_t)TT * BB * G3];    // x-gates fp32
__device__ __align__(16) float g_out0[(size_t)TT * BB * HH];  // layer-0 outputs
__device__ __align__(16) float g_hbuf[2][BB * HH];            // dbl-buffered h
__device__ int          g_cntg[16];
__device__ volatile int g_geng[16];

// ---------------- helpers ---------------------------------------------------
__device__ __forceinline__ float sigm_f(float x) {
    return __fdividef(1.0f, 1.0f + __expf(-x));
}
__device__ __forceinline__ float tanh_f(float x) {
    x = fminf(fmaxf(x, -15.0f), 15.0f);
    float e = __expf(-2.0f * x);
    return __fdividef(1.0f - e, 1.0f + e);
}
__device__ __forceinline__ uint32_t cvt_tf32(float f) {
    uint32_t u; asm("cvt.rna.tf32.f32 %0, %1;" : "=r"(u) : "f"(f)); return u;
}
__device__ __forceinline__ void mma_tf32(float* d, const uint32_t* a, const uint32_t* b) {
    asm volatile(
        "mma.sync.aligned.m16n8k8.row.col.f32.tf32.tf32.f32 "
        "{%0,%1,%2,%3}, {%4,%5,%6,%7}, {%8,%9}, {%0,%1,%2,%3};"
        : "+f"(d[0]), "+f"(d[1]), "+f"(d[2]), "+f"(d[3])
        : "r"(a[0]), "r"(a[1]), "r"(a[2]), "r"(a[3]), "r"(b[0]), "r"(b[1]));
}

// 8-CTA group barrier (per batch-group), generation counter survives replays
__device__ __forceinline__ void group_sync(int grp) {
    __syncthreads();
    if (threadIdx.x == 0) {
        __threadfence();
        int gen = g_geng[grp];
        if (atomicAdd(&g_cntg[grp], 1) == 7) {
            g_cntg[grp] = 0;
            __threadfence();
            g_geng[grp] = gen + 1;
        } else {
            while (g_geng[grp] == gen) { }
            __threadfence();
        }
    }
    __syncthreads();
}

// ---------------- weight reordering: W'[3j+g] = W[g*H + j] -----------------
__global__ void reorder_kernel(const float* __restrict__ Wx0, const float* __restrict__ bx0,
                               const float* __restrict__ Wh0, const float* __restrict__ bh0,
                               const float* __restrict__ Wx1, const float* __restrict__ bx1,
                               const float* __restrict__ Wh1, const float* __restrict__ bh1) {
    int tid = blockIdx.x * blockDim.x + threadIdx.x;
    int stride = gridDim.x * blockDim.x;
    for (int idx = tid; idx < G3 * DIN; idx += stride) {
        int n = idx / DIN, k = idx % DIN;
        int j = n / 3, g = n % 3;
        g_Wx0t[idx] = cvt_tf32(Wx0[(g * HH + j) * DIN + k]);
    }
    for (int idx = tid; idx < G3 * HH; idx += stride) {
        int n = idx / HH, k = idx % HH;
        int j = n / 3, g = n % 3;
        int s = (g * HH + j) * HH + k;
        g_Wh0p[idx] = Wh0[s];
        g_Wx1t[idx] = cvt_tf32(Wx1[s]);
        g_Wh1p[idx] = Wh1[s];
    }
    for (int idx = tid; idx < G3; idx += stride) {
        int j = idx / 3, g = idx % 3;
        g_bx0p[idx] = bx0[g * HH + j];
        g_bh0p[idx] = bh0[g * HH + j];
        g_bx1p[idx] = bx1[g * HH + j];
        g_bh1p[idx] = bh1[g * HH + j];
    }
}

// ---------------- tf32 mma.sync x-gates GEMM -------------------------------
// C[M,768] = X[M,K] @ W'[768,K]^T + b'.
// CTA tile 128x128, 8 warps (2x4), warp tile 64x32, kc=32 double-buffered.
// Smem rows padded to 36 words -> conflict-free fragment loads.
#define XS 36
#define XG_SMEM (2 * 2 * 128 * XS * 4)   // 73728 B

__global__ __launch_bounds__(256) void xgates_mma(const float* __restrict__ X,
                                                  const uint32_t* __restrict__ Wt,
                                                  const float* __restrict__ bp,
                                                  float* __restrict__ C, int K) {
    extern __shared__ uint32_t sm[];
    uint32_t* As = sm;                  // [2][128*XS]
    uint32_t* Bs = sm + 2 * 128 * XS;   // [2][128*XS]

    const int tid = threadIdx.x;
    const int wid = tid >> 5, lane = tid & 31;
    const int g = lane >> 2, t = lane & 3;
    const int warp_m = wid & 1, warp_n = wid >> 1;
    const int m0 = blockIdx.y * 128, n0 = blockIdx.x * 128;
    const int nc = K >> 5;

    float acc[4][4][4];
#pragma unroll
    for (int mt = 0; mt < 4; mt++)
#pragma unroll
        for (int nt = 0; nt < 4; nt++)
#pragma unroll
            for (int r = 0; r < 4; r++) acc[mt][nt][r] = 0.0f;

    const int lrow = tid >> 1;               // 0..127
    const int lk8  = (tid & 1) * 16;         // two float4 groups per row half
    // each thread loads 4 float4 of A and 4 of B per chunk:
    //   idx = tid + q*256 ; row = idx>>3 ; kq = (idx&7)*4
    uint4 ra[4], rb[4];
    (void)lrow; (void)lk8;

    auto ldg_chunk = [&](int c) {
#pragma unroll
        for (int q = 0; q < 4; q++) {
            int idx = tid + q * 256;
            int row = idx >> 3;
            int kq = (idx & 7) * 4;
            const float4 xv = *(const float4*)&X[(size_t)(m0 + row) * K + c * 32 + kq];
            ra[q].x = cvt_tf32(xv.x); ra[q].y = cvt_tf32(xv.y);
            ra[q].z = cvt_tf32(xv.z); ra[q].w = cvt_tf32(xv.w);
            rb[q] = *(const uint4*)&Wt[(size_t)(n0 + row) * K + c * 32 + kq];
        }
    };
    auto sts_chunk = [&](int buf) {
#pragma unroll
        for (int q = 0; q < 4; q++) {
            int idx = tid + q * 256;
            int row = idx >> 3;
            int kq = (idx & 7) * 4;
            *(uint4*)&As[buf * 128 * XS + row * XS + kq] = ra[q];
            *(uint4*)&Bs[buf * 128 * XS + row * XS + kq] = rb[q];
        }
    };

    ldg_chunk(0);
    sts_chunk(0);
    __syncthreads();

    int buf = 0;
    for (int c = 0; c < nc; c++) {
        if (c + 1 < nc) ldg_chunk(c + 1);

        const uint32_t* Ab = As + buf * 128 * XS;
        const uint32_t* Bb = Bs + buf * 128 * XS;
#pragma unroll
        for (int ks = 0; ks < 4; ks++) {
            const int k0 = ks * 8;
            uint32_t a[4][4], b[4][2];
#pragma unroll
            for (int mt = 0; mt < 4; mt++) {
                int r0 = warp_m * 64 + mt * 16;
                a[mt][0] = Ab[(r0 + g) * XS + k0 + t];
                a[mt][1] = Ab[(r0 + g + 8) * XS + k0 + t];
                a[mt][2] = Ab[(r0 + g) * XS + k0 + t + 4];
                a[mt][3] = Ab[(r0 + g + 8) * XS + k0 + t + 4];
            }
#pragma unroll
            for (int nt = 0; nt < 4; nt++) {
                int c0 = warp_n * 32 + nt * 8;
                b[nt][0] = Bb[(c0 + g) * XS + k0 + t];
                b[nt][1] = Bb[(c0 + g) * XS + k0 + t + 4];
            }
#pragma unroll
            for (int mt = 0; mt < 4; mt++)
#pragma unroll
                for (int nt = 0; nt < 4; nt++)
                    mma_tf32(acc[mt][nt], a[mt], b[nt]);
        }

        if (c + 1 < nc) sts_chunk(buf ^ 1);
        __syncthreads();
        buf ^= 1;
    }

    // epilogue: + bias, store fp32
    float bb0[4], bb1[4];
#pragma unroll
    for (int nt = 0; nt < 4; nt++) {
        int col = n0 + warp_n * 32 + nt * 8 + 2 * t;
        bb0[nt] = bp[col];
        bb1[nt] = bp[col + 1];
    }
#pragma unroll
    for (int mt = 0; mt < 4; mt++) {
        int r0 = m0 + warp_m * 64 + mt * 16;
#pragma unroll
        for (int nt = 0; nt < 4; nt++) {
            int col = n0 + warp_n * 32 + nt * 8 + 2 * t;
            float2 v0 = make_float2(acc[mt][nt][0] + bb0[nt], acc[mt][nt][1] + bb1[nt]);
            float2 v1 = make_float2(acc[mt][nt][2] + bb0[nt], acc[mt][nt][3] + bb1[nt]);
            *(float2*)&C[(size_t)(r0 + g) * G3 + col] = v0;
            *(float2*)&C[(size_t)(r0 + g + 8) * G3 + col] = v1;
        }
    }
}

// ---------------- persistent recurrent kernel (SIMT, group-barrier) --------
// Grid 8x16 = 128 CTAs, 256 threads, Wh' tile (256x96) smem-resident.
// CTA (cx, by): 64 batch rows x 96 interleaved gate cols. Sync only the
// 8 CTAs sharing `by` (they produce exactly the h rows this CTA consumes).
#define WHS_STRIDE 98
#define SMEM_REC ((256 * WHS_STRIDE + 32 * 64) * 4)

__global__ __launch_bounds__(256) void recurrent_kernel(
    const float* __restrict__ xg, const float* __restrict__ Whp,
    const float* __restrict__ bhp, const float* __restrict__ h0,
    const float* __restrict__ gamma, const float* __restrict__ beta,
    float* __restrict__ out_seq, float* __restrict__ final_h) {
    extern __shared__ float smemf[];
    float* Whs = smemf;
    float* As  = smemf + 256 * WHS_STRIDE;

    const int tid = threadIdx.x;
    const int tx = tid & 15, ty = tid >> 4;
    const int n0 = blockIdx.x * 96;
    const int b0 = blockIdx.y * 64;
    const int grp = blockIdx.y;
    const int c0 = 6 * tx;
    const int j0 = n0 / 3 + 2 * tx;

    for (int idx = tid; idx < 96 * 64; idx += 256) {
        int c = idx >> 6;
        int kqw = (idx & 63) * 4;
        float4 v = *(const float4*)&Whp[(size_t)(n0 + c) * HH + kqw];
        Whs[(kqw + 0) * WHS_STRIDE + c] = v.x;
        Whs[(kqw + 1) * WHS_STRIDE + c] = v.y;
        Whs[(kqw + 2) * WHS_STRIDE + c] = v.z;
        Whs[(kqw + 3) * WHS_STRIDE + c] = v.w;
    }

    float bias[6];
#pragma unroll
    for (int v = 0; v < 6; v++) bias[v] = bhp[n0 + c0 + v];

    float gm[4][2], bt[4][2];
#pragma unroll
    for (int i = 0; i < 4; i++) {
        int b = b0 + ty * 4 + i;
#pragma unroll
        for (int u = 0; u < 2; u++) {
            gm[i][u] = gamma[b * HH + j0 + u];
            bt[i][u] = beta [b * HH + j0 + u];
        }
    }

    {
        int jb = n0 / 3;
        for (int idx = tid; idx < 64 * 32; idx += 256) {
            int rr = idx >> 5, cc = idx & 31;
            int off = (b0 + rr) * HH + jb + cc;
            g_hbuf[0][off] = h0[off];
        }
    }
    group_sync(grp);

    for (int t = 0; t < TT; t++) {
        const float* hcur = g_hbuf[t & 1];
        float* hnext = g_hbuf[(t + 1) & 1];

        float acc[4][6];
#pragma unroll
        for (int i = 0; i < 4; i++)
#pragma unroll
            for (int v = 0; v < 6; v++) acc[i][v] = bias[v];

        float4 pre[2];
#pragma unroll
        for (int p = 0; p < 2; p++) {
            int i = tid + p * 256;
            int rr = i >> 3, kq = (i & 7) * 4;
            pre[p] = __ldcv((const float4*)&hcur[(size_t)(b0 + rr) * HH + kq]);
        }

        for (int kc = 0; kc < HH; kc += 32) {
            __syncthreads();
#pragma unroll
            for (int p = 0; p < 2; p++) {
                int i = tid + p * 256;
                int rr = i >> 3, kq = (i & 7) * 4;
                As[(kq + 0) * 64 + rr] = pre[p].x;
                As[(kq + 1) * 64 + rr] = pre[p].y;
                As[(kq + 2) * 64 + rr] = pre[p].z;
                As[(kq + 3) * 64 + rr] = pre[p].w;
            }
            __syncthreads();
            if (kc + 32 < HH) {
#pragma unroll
                for (int p = 0; p < 2; p++) {
                    int i = tid + p * 256;
                    int rr = i >> 3, kq = (i & 7) * 4;
                    pre[p] = __ldcv((const float4*)&hcur[(size_t)(b0 + rr) * HH + kc + 32 + kq]);
                }
            }
            const float* Wk = Whs + (size_t)kc * WHS_STRIDE + c0;
#pragma unroll
            for (int k = 0; k < 32; k++) {
                float4 av = *(const float4*)&As[k * 64 + ty * 4];
                const float2* wr2 = (const float2*)(Wk + k * WHS_STRIDE);
                float2 w01 = wr2[0], w23 = wr2[1], w45 = wr2[2];
                float a[4] = {av.x, av.y, av.z, av.w};
                float w[6] = {w01.x, w01.y, w23.x, w23.y, w45.x, w45.y};
#pragma unroll
                for (int i = 0; i < 4; i++)
#pragma unroll
                    for (int v = 0; v < 6; v++)
                        acc[i][v] = fmaf(a[i], w[v], acc[i][v]);
            }
        }

#pragma unroll
        for (int i = 0; i < 4; i++) {
            int b = b0 + ty * 4 + i;
            const float* xgp = xg + ((size_t)t * BB + b) * G3 + n0 + c0;
            float hv[2];
#pragma unroll
            for (int u = 0; u < 2; u++) {
                float z  = sigm_f(xgp[3 * u + 0] + acc[i][3 * u + 0]);
                float rr = sigm_f(xgp[3 * u + 1] + acc[i][3 * u + 1]);
                float nn = tanh_f(xgp[3 * u + 2] + rr * acc[i][3 * u + 2]);
                float hp = __ldcv(&hcur[(size_t)b * HH + j0 + u]);
                float h  = nn + z * (hp - nn);
                hv[u] = fmaf(gm[i][u], h, bt[i][u]);
            }
            float2 hv2 = make_float2(hv[0], hv[1]);
            *(float2*)&hnext[(size_t)b * HH + j0] = hv2;
            *(float2*)&out_seq[((size_t)t * BB + b) * HH + j0] = hv2;
            if (t == TT - 1)
                *(float2*)&final_h[(size_t)b * HH + j0] = hv2;
        }
        group_sync(grp);
    }
}

// ---------------- host launcher -------------------------------------------
extern "C" void kernel_launch(void* const* d_in, const int* in_sizes, int n_in,
                              void* d_out, int out_size) {
    (void)in_sizes; (void)n_in; (void)out_size;
    const float* x      = (const float*)d_in[0];
    const float* init_s = (const float*)d_in[1];
    const float* gammas = (const float*)d_in[2];
    const float* betas  = (const float*)d_in[3];
    const float* Wx0 = (const float*)d_in[4];
    const float* bx0 = (const float*)d_in[5];
    const float* Wh0 = (const float*)d_in[6];
    const float* bh0 = (const float*)d_in[7];
    const float* Wx1 = (const float*)d_in[8];
    const float* bx1 = (const float*)d_in[9];
    const float* Wh1 = (const float*)d_in[10];
    const float* bh1 = (const float*)d_in[11];
    float* out = (float*)d_out;

    uint32_t *pWx0t, *pWx1t;
    float *pWh0p, *pWh1p, *pbx0p, *pbh0p, *pbx1p, *pbh1p, *pxg, *pout0;
    cudaGetSymbolAddress((void**)&pWx0t, g_Wx0t);
    cudaGetSymbolAddress((void**)&pWx1t, g_Wx1t);
    cudaGetSymbolAddress((void**)&pWh0p, g_Wh0p);
    cudaGetSymbolAddress((void**)&pWh1p, g_Wh1p);
    cudaGetSymbolAddress((void**)&pbx0p, g_bx0p);
    cudaGetSymbolAddress((void**)&pbh0p, g_bh0p);
    cudaGetSymbolAddress((void**)&pbx1p, g_bx1p);
    cudaGetSymbolAddress((void**)&pbh1p, g_bh1p);
    cudaGetSymbolAddress((void**)&pxg,   g_xg);
    cudaGetSymbolAddress((void**)&pout0, g_out0);

    cudaFuncSetAttribute(recurrent_kernel,
                         cudaFuncAttributeMaxDynamicSharedMemorySize, SMEM_REC);
    cudaFuncSetAttribute(xgates_mma,
                         cudaFuncAttributeMaxDynamicSharedMemorySize, XG_SMEM);

    const size_t out1_elems = (size_t)TT * BB * HH;

    reorder_kernel<<<768, 256>>>(Wx0, bx0, Wh0, bh0, Wx1, bx1, Wh1, bh1);

    // layer 0
    xgates_mma<<<dim3(6, 1024), 256, XG_SMEM>>>(x, pWx0t, pbx0p, pxg, DIN);
    recurrent_kernel<<<dim3(8, 16), 256, SMEM_REC>>>(
        pxg, pWh0p, pbh0p, init_s, gammas, betas,
        pout0, out + out1_elems);

    // layer 1
    xgates_mma<<<dim3(6, 1024), 256, XG_SMEM>>>(pout0, pWx1t, pbx1p, pxg, HH);
    recurrent_kernel<<<dim3(8, 16), 256, SMEM_REC>>>(
        pxg, pWh1p, pbh1p, init_s + BB * HH,
        gammas + (size_t)BB * HH, betas + (size_t)BB * HH,
        out, out + out1_elems + (size_t)BB * HH);
}

// round 7
// speedup vs baseline: 1.8172x; 1.5554x over previous
#include <cuda_runtime.h>
#include <cstdint>

#define TT  128
#define BB  1024
#define DIN 128
#define HH  256
#define G3  768   // 3*H, gate-interleaved columns

// ---------------- device scratch (static globals; no allocations) ----------
__device__ __align__(16) uint32_t g_Wx0t[G3 * DIN];  // tf32 bits, [col][k]
__device__ __align__(16) uint32_t g_Wx1t[G3 * HH];
__device__ __align__(16) float g_Wh0p[G3 * HH];
__device__ __align__(16) float g_Wh1p[G3 * HH];
__device__ float g_bx0p[G3];
__device__ float g_bh0p[G3];
__device__ float g_bx1p[G3];
__device__ float g_bh1p[G3];
__device__ __align__(16) float g_xg[(size_t)TT * BB * G3];    // x-gates fp32
__device__ __align__(16) float g_out0[(size_t)TT * BB * HH];  // layer-0 outputs
__device__ __align__(16) float g_hbuf[2][BB * HH];            // dbl-buffered h
__device__ int          g_cntg[16];
__device__ volatile int g_geng[16];

// ---------------- helpers ---------------------------------------------------
__device__ __forceinline__ float sigm_f(float x) {
    return __fdividef(1.0f, 1.0f + __expf(-x));
}
__device__ __forceinline__ float tanh_f(float x) {
    x = fminf(fmaxf(x, -15.0f), 15.0f);
    float e = __expf(-2.0f * x);
    return __fdividef(1.0f - e, 1.0f + e);
}
__device__ __forceinline__ uint32_t cvt_tf32(float f) {
    uint32_t u; asm("cvt.rna.tf32.f32 %0, %1;" : "=r"(u) : "f"(f)); return u;
}
__device__ __forceinline__ void mma_tf32(float* d, const uint32_t* a, const uint32_t* b) {
    asm volatile(
        "mma.sync.aligned.m16n8k8.row.col.f32.tf32.tf32.f32 "
        "{%0,%1,%2,%3}, {%4,%5,%6,%7}, {%8,%9}, {%0,%1,%2,%3};"
        : "+f"(d[0]), "+f"(d[1]), "+f"(d[2]), "+f"(d[3])
        : "r"(a[0]), "r"(a[1]), "r"(a[2]), "r"(a[3]), "r"(b[0]), "r"(b[1]));
}

// 8-CTA group barrier (per batch-group), generation counter survives replays
__device__ __forceinline__ void group_sync(int grp) {
    __syncthreads();
    if (threadIdx.x == 0) {
        __threadfence();
        int gen = g_geng[grp];
        if (atomicAdd(&g_cntg[grp], 1) == 7) {
            g_cntg[grp] = 0;
            __threadfence();
            g_geng[grp] = gen + 1;
        } else {
            while (g_geng[grp] == gen) { }
            __threadfence();
        }
    }
    __syncthreads();
}

// ---------------- weight reordering: W'[3j+g] = W[g*H + j] -----------------
__global__ void reorder_kernel(const float* __restrict__ Wx0, const float* __restrict__ bx0,
                               const float* __restrict__ Wh0, const float* __restrict__ bh0,
                               const float* __restrict__ Wx1, const float* __restrict__ bx1,
                               const float* __restrict__ Wh1, const float* __restrict__ bh1) {
    int tid = blockIdx.x * blockDim.x + threadIdx.x;
    int stride = gridDim.x * blockDim.x;
    for (int idx = tid; idx < G3 * DIN; idx += stride) {
        int n = idx / DIN, k = idx % DIN;
        int j = n / 3, g = n % 3;
        g_Wx0t[idx] = cvt_tf32(Wx0[(g * HH + j) * DIN + k]);
    }
    for (int idx = tid; idx < G3 * HH; idx += stride) {
        int n = idx / HH, k = idx % HH;
        int j = n / 3, g = n % 3;
        int s = (g * HH + j) * HH + k;
        g_Wh0p[idx] = Wh0[s];
        g_Wx1t[idx] = cvt_tf32(Wx1[s]);
        g_Wh1p[idx] = Wh1[s];
    }
    for (int idx = tid; idx < G3; idx += stride) {
        int j = idx / 3, g = idx % 3;
        g_bx0p[idx] = bx0[g * HH + j];
        g_bh0p[idx] = bh0[g * HH + j];
        g_bx1p[idx] = bx1[g * HH + j];
        g_bh1p[idx] = bh1[g * HH + j];
    }
}

// ---------------- tf32 mma.sync x-gates GEMM (unchanged, proven) -----------
#define XS 36
#define XG_SMEM (2 * 2 * 128 * XS * 4)   // 73728 B

__global__ __launch_bounds__(256) void xgates_mma(const float* __restrict__ X,
                                                  const uint32_t* __restrict__ Wt,
                                                  const float* __restrict__ bp,
                                                  float* __restrict__ C, int K) {
    extern __shared__ uint32_t sm[];
    uint32_t* As = sm;                  // [2][128*XS]
    uint32_t* Bs = sm + 2 * 128 * XS;   // [2][128*XS]

    const int tid = threadIdx.x;
    const int wid = tid >> 5, lane = tid & 31;
    const int g = lane >> 2, t = lane & 3;
    const int warp_m = wid & 1, warp_n = wid >> 1;
    const int m0 = blockIdx.y * 128, n0 = blockIdx.x * 128;
    const int nc = K >> 5;

    float acc[4][4][4];
#pragma unroll
    for (int mt = 0; mt < 4; mt++)
#pragma unroll
        for (int nt = 0; nt < 4; nt++)
#pragma unroll
            for (int r = 0; r < 4; r++) acc[mt][nt][r] = 0.0f;

    uint4 ra[4], rb[4];

    auto ldg_chunk = [&](int c) {
#pragma unroll
        for (int q = 0; q < 4; q++) {
            int idx = tid + q * 256;
            int row = idx >> 3;
            int kq = (idx & 7) * 4;
            const float4 xv = *(const float4*)&X[(size_t)(m0 + row) * K + c * 32 + kq];
            ra[q].x = cvt_tf32(xv.x); ra[q].y = cvt_tf32(xv.y);
            ra[q].z = cvt_tf32(xv.z); ra[q].w = cvt_tf32(xv.w);
            rb[q] = *(const uint4*)&Wt[(size_t)(n0 + row) * K + c * 32 + kq];
        }
    };
    auto sts_chunk = [&](int buf) {
#pragma unroll
        for (int q = 0; q < 4; q++) {
            int idx = tid + q * 256;
            int row = idx >> 3;
            int kq = (idx & 7) * 4;
            *(uint4*)&As[buf * 128 * XS + row * XS + kq] = ra[q];
            *(uint4*)&Bs[buf * 128 * XS + row * XS + kq] = rb[q];
        }
    };

    ldg_chunk(0);
    sts_chunk(0);
    __syncthreads();

    int buf = 0;
    for (int c = 0; c < nc; c++) {
        if (c + 1 < nc) ldg_chunk(c + 1);

        const uint32_t* Ab = As + buf * 128 * XS;
        const uint32_t* Bb = Bs + buf * 128 * XS;
#pragma unroll
        for (int ks = 0; ks < 4; ks++) {
            const int k0 = ks * 8;
            uint32_t a[4][4], b[4][2];
#pragma unroll
            for (int mt = 0; mt < 4; mt++) {
                int r0 = warp_m * 64 + mt * 16;
                a[mt][0] = Ab[(r0 + g) * XS + k0 + t];
                a[mt][1] = Ab[(r0 + g + 8) * XS + k0 + t];
                a[mt][2] = Ab[(r0 + g) * XS + k0 + t + 4];
                a[mt][3] = Ab[(r0 + g + 8) * XS + k0 + t + 4];
            }
#pragma unroll
            for (int nt = 0; nt < 4; nt++) {
                int c0 = warp_n * 32 + nt * 8;
                b[nt][0] = Bb[(c0 + g) * XS + k0 + t];
                b[nt][1] = Bb[(c0 + g) * XS + k0 + t + 4];
            }
#pragma unroll
            for (int mt = 0; mt < 4; mt++)
#pragma unroll
                for (int nt = 0; nt < 4; nt++)
                    mma_tf32(acc[mt][nt], a[mt], b[nt]);
        }

        if (c + 1 < nc) sts_chunk(buf ^ 1);
        __syncthreads();
        buf ^= 1;
    }

    float bb0[4], bb1[4];
#pragma unroll
    for (int nt = 0; nt < 4; nt++) {
        int col = n0 + warp_n * 32 + nt * 8 + 2 * t;
        bb0[nt] = bp[col];
        bb1[nt] = bp[col + 1];
    }
#pragma unroll
    for (int mt = 0; mt < 4; mt++) {
        int r0 = m0 + warp_m * 64 + mt * 16;
#pragma unroll
        for (int nt = 0; nt < 4; nt++) {
            int col = n0 + warp_n * 32 + nt * 8 + 2 * t;
            float2 v0 = make_float2(acc[mt][nt][0] + bb0[nt], acc[mt][nt][1] + bb1[nt]);
            float2 v1 = make_float2(acc[mt][nt][2] + bb0[nt], acc[mt][nt][3] + bb1[nt]);
            *(float2*)&C[(size_t)(r0 + g) * G3 + col] = v0;
            *(float2*)&C[(size_t)(r0 + g + 8) * G3 + col] = v1;
        }
    }
}

// ---------------- persistent recurrent kernel: tf32 mma.sync ---------------
// Grid 8x16 = 128 CTAs, 256 threads.  CTA (cx, by): 64 batch rows x 96 gate
// cols (interleaved).  Wh' tile converted to tf32 smem once; per step the
// h tile streams through smem (ldcv->cvt), GEMM via m16n8k8, accumulators
// staged in smem so elementwise keeps the proven (row, zrn-triple) mapping.
#define RWS 260                 // Ws stride (words): (4g+t) banks distinct
#define RAS 36                  // As stride
#define RGS 100                 // Gs stride
#define SMEM_REC2 ((96 * RWS + 64 * RAS + 64 * RGS) * 4)   // 134656 B

__global__ __launch_bounds__(256) void recurrent_mma(
    const float* __restrict__ xg, const float* __restrict__ Whp,
    const float* __restrict__ bhp, const float* __restrict__ h0,
    const float* __restrict__ gamma, const float* __restrict__ beta,
    float* __restrict__ out_seq, float* __restrict__ final_h) {
    extern __shared__ uint32_t sm2[];
    uint32_t* Ws = sm2;                        // [96][RWS] tf32 Wh'
    uint32_t* As = sm2 + 96 * RWS;             // [64][RAS] tf32 h chunk
    float*    Gs = (float*)(sm2 + 96 * RWS + 64 * RAS);  // [64][RGS] h_gates

    const int tid = threadIdx.x;
    const int wid = tid >> 5, lane = tid & 31;
    const int g = lane >> 2, t = lane & 3;
    const int warp_m = wid & 1, warp_n = wid >> 1;
    const int n0 = blockIdx.x * 96;
    const int b0 = blockIdx.y * 64;
    const int grp = blockIdx.y;
    const int tx = tid & 15, ty = tid >> 4;
    const int c0 = 6 * tx;
    const int j0 = n0 / 3 + 2 * tx;

    // one-time: Wh' (gate-interleaved [n][k]) -> tf32 smem
    for (int idx = tid; idx < 96 * 256; idx += 256) {
        int n = idx >> 8, k = idx & 255;
        Ws[n * RWS + k] = cvt_tf32(Whp[(size_t)(n0 + n) * HH + k]);
    }

    float bias[6];
#pragma unroll
    for (int v = 0; v < 6; v++) bias[v] = bhp[n0 + c0 + v];

    float gm[4][2], bt[4][2];
#pragma unroll
    for (int i = 0; i < 4; i++) {
        int b = b0 + ty * 4 + i;
#pragma unroll
        for (int u = 0; u < 2; u++) {
            gm[i][u] = gamma[b * HH + j0 + u];
            bt[i][u] = beta [b * HH + j0 + u];
        }
    }

    {   // init hidden state
        int jb = n0 / 3;
        for (int idx = tid; idx < 64 * 32; idx += 256) {
            int rr = idx >> 5, cc = idx & 31;
            int off = (b0 + rr) * HH + jb + cc;
            g_hbuf[0][off] = h0[off];
        }
    }
    group_sync(grp);

    for (int step = 0; step < TT; step++) {
        const float* hcur = g_hbuf[step & 1];
        float* hnext = g_hbuf[(step + 1) & 1];

        float acc[2][3][4];
#pragma unroll
        for (int mt = 0; mt < 2; mt++)
#pragma unroll
            for (int nt = 0; nt < 3; nt++)
#pragma unroll
                for (int r = 0; r < 4; r++) acc[mt][nt][r] = 0.0f;

        // prefetch chunk 0 of h (ldcv: other SMs wrote it last step)
        float4 pre[2];
#pragma unroll
        for (int p = 0; p < 2; p++) {
            int idx = tid + p * 256;
            int row = idx >> 3, kq = (idx & 7) * 4;
            pre[p] = __ldcv((const float4*)&hcur[(size_t)(b0 + row) * HH + kq]);
        }

        for (int kc = 0; kc < HH; kc += 32) {
            __syncthreads();
#pragma unroll
            for (int p = 0; p < 2; p++) {
                int idx = tid + p * 256;
                int row = idx >> 3, kq = (idx & 7) * 4;
                uint4 cv;
                cv.x = cvt_tf32(pre[p].x); cv.y = cvt_tf32(pre[p].y);
                cv.z = cvt_tf32(pre[p].z); cv.w = cvt_tf32(pre[p].w);
                *(uint4*)&As[row * RAS + kq] = cv;
            }
            __syncthreads();
            if (kc + 32 < HH) {
#pragma unroll
                for (int p = 0; p < 2; p++) {
                    int idx = tid + p * 256;
                    int row = idx >> 3, kq = (idx & 7) * 4;
                    pre[p] = __ldcv((const float4*)&hcur[(size_t)(b0 + row) * HH + kc + 32 + kq]);
                }
            }
#pragma unroll
            for (int ks = 0; ks < 4; ks++) {
                const int k0 = ks * 8;
                uint32_t a[2][4], b[3][2];
#pragma unroll
                for (int mt = 0; mt < 2; mt++) {
                    int r0 = warp_m * 32 + mt * 16;
                    a[mt][0] = As[(r0 + g) * RAS + k0 + t];
                    a[mt][1] = As[(r0 + g + 8) * RAS + k0 + t];
                    a[mt][2] = As[(r0 + g) * RAS + k0 + t + 4];
                    a[mt][3] = As[(r0 + g + 8) * RAS + k0 + t + 4];
                }
#pragma unroll
                for (int nt = 0; nt < 3; nt++) {
                    int cb = warp_n * 24 + nt * 8;
                    b[nt][0] = Ws[(cb + g) * RWS + kc + k0 + t];
                    b[nt][1] = Ws[(cb + g) * RWS + kc + k0 + t + 4];
                }
#pragma unroll
                for (int mt = 0; mt < 2; mt++)
#pragma unroll
                    for (int nt = 0; nt < 3; nt++)
                        mma_tf32(acc[mt][nt], a[mt], b[nt]);
            }
        }

        // stage h_gates to smem (decouple MMA fragment layout from gate math)
#pragma unroll
        for (int mt = 0; mt < 2; mt++) {
            int row = warp_m * 32 + mt * 16 + g;
#pragma unroll
            for (int nt = 0; nt < 3; nt++) {
                int col = warp_n * 24 + nt * 8 + 2 * t;
                *(float2*)&Gs[row * RGS + col] =
                    make_float2(acc[mt][nt][0], acc[mt][nt][1]);
                *(float2*)&Gs[(row + 8) * RGS + col] =
                    make_float2(acc[mt][nt][2], acc[mt][nt][3]);
            }
        }
        __syncthreads();

        // gates + FiLM + writes (proven mapping)
#pragma unroll
        for (int i = 0; i < 4; i++) {
            int b = b0 + ty * 4 + i;
            int rl = ty * 4 + i;
            const float* xgp = xg + ((size_t)step * BB + b) * G3 + n0 + c0;
            const float* gr = &Gs[rl * RGS + c0];
            float hv[2];
#pragma unroll
            for (int u = 0; u < 2; u++) {
                float z  = sigm_f(xgp[3 * u + 0] + gr[3 * u + 0] + bias[3 * u + 0]);
                float rr = sigm_f(xgp[3 * u + 1] + gr[3 * u + 1] + bias[3 * u + 1]);
                float nn = tanh_f(xgp[3 * u + 2] + rr * (gr[3 * u + 2] + bias[3 * u + 2]));
                float hp = __ldcv(&hcur[(size_t)b * HH + j0 + u]);
                float h  = nn + z * (hp - nn);
                hv[u] = fmaf(gm[i][u], h, bt[i][u]);
            }
            float2 hv2 = make_float2(hv[0], hv[1]);
            *(float2*)&hnext[(size_t)b * HH + j0] = hv2;
            *(float2*)&out_seq[((size_t)step * BB + b) * HH + j0] = hv2;
            if (step == TT - 1)
                *(float2*)&final_h[(size_t)b * HH + j0] = hv2;
        }
        group_sync(grp);
    }
}

// ---------------- host launcher -------------------------------------------
extern "C" void kernel_launch(void* const* d_in, const int* in_sizes, int n_in,
                              void* d_out, int out_size) {
    (void)in_sizes; (void)n_in; (void)out_size;
    const float* x      = (const float*)d_in[0];
    const float* init_s = (const float*)d_in[1];
    const float* gammas = (const float*)d_in[2];
    const float* betas  = (const float*)d_in[3];
    const float* Wx0 = (const float*)d_in[4];
    const float* bx0 = (const float*)d_in[5];
    const float* Wh0 = (const float*)d_in[6];
    const float* bh0 = (const float*)d_in[7];
    const float* Wx1 = (const float*)d_in[8];
    const float* bx1 = (const float*)d_in[9];
    const float* Wh1 = (const float*)d_in[10];
    const float* bh1 = (const float*)d_in[11];
    float* out = (float*)d_out;

    uint32_t *pWx0t, *pWx1t;
    float *pWh0p, *pWh1p, *pbx0p, *pbh0p, *pbx1p, *pbh1p, *pxg, *pout0;
    cudaGetSymbolAddress((void**)&pWx0t, g_Wx0t);
    cudaGetSymbolAddress((void**)&pWx1t, g_Wx1t);
    cudaGetSymbolAddress((void**)&pWh0p, g_Wh0p);
    cudaGetSymbolAddress((void**)&pWh1p, g_Wh1p);
    cudaGetSymbolAddress((void**)&pbx0p, g_bx0p);
    cudaGetSymbolAddress((void**)&pbh0p, g_bh0p);
    cudaGetSymbolAddress((void**)&pbx1p, g_bx1p);
    cudaGetSymbolAddress((void**)&pbh1p, g_bh1p);
    cudaGetSymbolAddress((void**)&pxg,   g_xg);
    cudaGetSymbolAddress((void**)&pout0, g_out0);

    cudaFuncSetAttribute(recurrent_mma,
                         cudaFuncAttributeMaxDynamicSharedMemorySize, SMEM_REC2);
    cudaFuncSetAttribute(xgates_mma,
                         cudaFuncAttributeMaxDynamicSharedMemorySize, XG_SMEM);

    const size_t out1_elems = (size_t)TT * BB * HH;

    reorder_kernel<<<768, 256>>>(Wx0, bx0, Wh0, bh0, Wx1, bx1, Wh1, bh1);

    // layer 0
    xgates_mma<<<dim3(6, 1024), 256, XG_SMEM>>>(x, pWx0t, pbx0p, pxg, DIN);
    recurrent_mma<<<dim3(8, 16), 256, SMEM_REC2>>>(
        pxg, pWh0p, pbh0p, init_s, gammas, betas,
        pout0, out + out1_elems);

    // layer 1
    xgates_mma<<<dim3(6, 1024), 256, XG_SMEM>>>(pout0, pWx1t, pbx1p, pxg, HH);
    recurrent_mma<<<dim3(8, 16), 256, SMEM_REC2>>>(
        pxg, pWh1p, pbh1p, init_s + BB * HH,
        gammas + (size_t)BB * HH, betas + (size_t)BB * HH,
        out, out + out1_elems + (size_t)BB * HH);
}

// round 8
// speedup vs baseline: 2.2167x; 1.2198x over previous
#include <cuda_runtime.h>
#include <cstdint>

#define TT  128
#define BB  1024
#define DIN 128
#define HH  256
#define G3  768   // 3*H, gate-interleaved columns

// ---------------- device scratch (static globals; no allocations) ----------
__device__ __align__(16) uint32_t g_Wx0t[G3 * DIN];  // tf32 bits, [col][k]
__device__ __align__(16) uint32_t g_Wx1t[G3 * HH];
__device__ __align__(16) float g_Wh0p[G3 * HH];
__device__ __align__(16) float g_Wh1p[G3 * HH];
__device__ float g_bx0p[G3];
__device__ float g_bh0p[G3];
__device__ float g_bx1p[G3];
__device__ float g_bh1p[G3];
__device__ __align__(16) float g_xg[(size_t)TT * BB * G3];    // x-gates fp32
__device__ __align__(16) float g_out0[(size_t)TT * BB * HH];  // layer-0 outputs
__device__ __align__(16) float g_hbuf[2][BB * HH];            // dbl-buffered h
__device__ int          g_cntg[16];
__device__ volatile int g_geng[16];

// ---------------- helpers ---------------------------------------------------
__device__ __forceinline__ float sigm_f(float x) {
    return __fdividef(1.0f, 1.0f + __expf(-x));
}
__device__ __forceinline__ float tanh_f(float x) {
    x = fminf(fmaxf(x, -15.0f), 15.0f);
    float e = __expf(-2.0f * x);
    return __fdividef(1.0f - e, 1.0f + e);
}
__device__ __forceinline__ uint32_t cvt_tf32(float f) {
    uint32_t u; asm("cvt.rna.tf32.f32 %0, %1;" : "=r"(u) : "f"(f)); return u;
}
__device__ __forceinline__ void mma_tf32(float* d, const uint32_t* a, const uint32_t* b) {
    asm volatile(
        "mma.sync.aligned.m16n8k8.row.col.f32.tf32.tf32.f32 "
        "{%0,%1,%2,%3}, {%4,%5,%6,%7}, {%8,%9}, {%0,%1,%2,%3};"
        : "+f"(d[0]), "+f"(d[1]), "+f"(d[2]), "+f"(d[3])
        : "r"(a[0]), "r"(a[1]), "r"(a[2]), "r"(a[3]), "r"(b[0]), "r"(b[1]));
}

// 8-CTA group barrier (per batch-group), generation counter survives replays
__device__ __forceinline__ void group_sync(int grp) {
    __syncthreads();
    if (threadIdx.x == 0) {
        __threadfence();
        int gen = g_geng[grp];
        if (atomicAdd(&g_cntg[grp], 1) == 7) {
            g_cntg[grp] = 0;
            __threadfence();
            g_geng[grp] = gen + 1;
        } else {
            while (g_geng[grp] == gen) { }
            __threadfence();
        }
    }
    __syncthreads();
}

// ---------------- weight reordering: W'[3j+g] = W[g*H + j] -----------------
__global__ void reorder_kernel(const float* __restrict__ Wx0, const float* __restrict__ bx0,
                               const float* __restrict__ Wh0, const float* __restrict__ bh0,
                               const float* __restrict__ Wx1, const float* __restrict__ bx1,
                               const float* __restrict__ Wh1, const float* __restrict__ bh1) {
    int tid = blockIdx.x * blockDim.x + threadIdx.x;
    int stride = gridDim.x * blockDim.x;
    for (int idx = tid; idx < G3 * DIN; idx += stride) {
        int n = idx / DIN, k = idx % DIN;
        int j = n / 3, g = n % 3;
        g_Wx0t[idx] = cvt_tf32(Wx0[(g * HH + j) * DIN + k]);
    }
    for (int idx = tid; idx < G3 * HH; idx += stride) {
        int n = idx / HH, k = idx % HH;
        int j = n / 3, g = n % 3;
        int s = (g * HH + j) * HH + k;
        g_Wh0p[idx] = Wh0[s];
        g_Wx1t[idx] = cvt_tf32(Wx1[s]);
        g_Wh1p[idx] = Wh1[s];
    }
    for (int idx = tid; idx < G3; idx += stride) {
        int j = idx / 3, g = idx % 3;
        g_bx0p[idx] = bx0[g * HH + j];
        g_bh0p[idx] = bh0[g * HH + j];
        g_bx1p[idx] = bx1[g * HH + j];
        g_bh1p[idx] = bh1[g * HH + j];
    }
}

// ---------------- tf32 mma.sync x-gates GEMM -------------------------------
// CTA tile 128x128, 8 warps (2x4), warp tile 64x32, kc=32 double-buffered.
// launch_bounds(256,2): cap 128 regs -> 2 CTAs/SM (was 1, occ-capped at 12%).
#define XS 36
#define XG_SMEM (2 * 2 * 128 * XS * 4)   // 73728 B

__global__ __launch_bounds__(256, 2) void xgates_mma(const float* __restrict__ X,
                                                     const uint32_t* __restrict__ Wt,
                                                     const float* __restrict__ bp,
                                                     float* __restrict__ C, int K) {
    extern __shared__ uint32_t sm[];
    uint32_t* As = sm;                  // [2][128*XS]
    uint32_t* Bs = sm + 2 * 128 * XS;   // [2][128*XS]

    const int tid = threadIdx.x;
    const int wid = tid >> 5, lane = tid & 31;
    const int g = lane >> 2, t = lane & 3;
    const int warp_m = wid & 1, warp_n = wid >> 1;
    const int m0 = blockIdx.y * 128, n0 = blockIdx.x * 128;
    const int nc = K >> 5;

    float acc[4][4][4];
#pragma unroll
    for (int mt = 0; mt < 4; mt++)
#pragma unroll
        for (int nt = 0; nt < 4; nt++)
#pragma unroll
            for (int r = 0; r < 4; r++) acc[mt][nt][r] = 0.0f;

    uint4 ra[4], rb[4];

    auto ldg_chunk = [&](int c) {
#pragma unroll
        for (int q = 0; q < 4; q++) {
            int idx = tid + q * 256;
            int row = idx >> 3;
            int kq = (idx & 7) * 4;
            const float4 xv = *(const float4*)&X[(size_t)(m0 + row) * K + c * 32 + kq];
            ra[q].x = cvt_tf32(xv.x); ra[q].y = cvt_tf32(xv.y);
            ra[q].z = cvt_tf32(xv.z); ra[q].w = cvt_tf32(xv.w);
            rb[q] = *(const uint4*)&Wt[(size_t)(n0 + row) * K + c * 32 + kq];
        }
    };
    auto sts_chunk = [&](int buf) {
#pragma unroll
        for (int q = 0; q < 4; q++) {
            int idx = tid + q * 256;
            int row = idx >> 3;
            int kq = (idx & 7) * 4;
            *(uint4*)&As[buf * 128 * XS + row * XS + kq] = ra[q];
            *(uint4*)&Bs[buf * 128 * XS + row * XS + kq] = rb[q];
        }
    };

    ldg_chunk(0);
    sts_chunk(0);
    __syncthreads();

    int buf = 0;
    for (int c = 0; c < nc; c++) {
        if (c + 1 < nc) ldg_chunk(c + 1);

        const uint32_t* Ab = As + buf * 128 * XS;
        const uint32_t* Bb = Bs + buf * 128 * XS;
#pragma unroll
        for (int ks = 0; ks < 4; ks++) {
            const int k0 = ks * 8;
            uint32_t a[4][4], b[4][2];
#pragma unroll
            for (int mt = 0; mt < 4; mt++) {
                int r0 = warp_m * 64 + mt * 16;
                a[mt][0] = Ab[(r0 + g) * XS + k0 + t];
                a[mt][1] = Ab[(r0 + g + 8) * XS + k0 + t];
                a[mt][2] = Ab[(r0 + g) * XS + k0 + t + 4];
                a[mt][3] = Ab[(r0 + g + 8) * XS + k0 + t + 4];
            }
#pragma unroll
            for (int nt = 0; nt < 4; nt++) {
                int c0 = warp_n * 32 + nt * 8;
                b[nt][0] = Bb[(c0 + g) * XS + k0 + t];
                b[nt][1] = Bb[(c0 + g) * XS + k0 + t + 4];
            }
#pragma unroll
            for (int mt = 0; mt < 4; mt++)
#pragma unroll
                for (int nt = 0; nt < 4; nt++)
                    mma_tf32(acc[mt][nt], a[mt], b[nt]);
        }

        if (c + 1 < nc) sts_chunk(buf ^ 1);
        __syncthreads();
        buf ^= 1;
    }

    float bb0[4], bb1[4];
#pragma unroll
    for (int nt = 0; nt < 4; nt++) {
        int col = n0 + warp_n * 32 + nt * 8 + 2 * t;
        bb0[nt] = bp[col];
        bb1[nt] = bp[col + 1];
    }
#pragma unroll
    for (int mt = 0; mt < 4; mt++) {
        int r0 = m0 + warp_m * 64 + mt * 16;
#pragma unroll
        for (int nt = 0; nt < 4; nt++) {
            int col = n0 + warp_n * 32 + nt * 8 + 2 * t;
            float2 v0 = make_float2(acc[mt][nt][0] + bb0[nt], acc[mt][nt][1] + bb1[nt]);
            float2 v1 = make_float2(acc[mt][nt][2] + bb0[nt], acc[mt][nt][3] + bb1[nt]);
            *(float2*)&C[(size_t)(r0 + g) * G3 + col] = v0;
            *(float2*)&C[(size_t)(r0 + g + 8) * G3 + col] = v1;
        }
    }
}

// ---------------- persistent recurrent kernel: tf32 mma.sync ---------------
// Grid 8x16 = 128 CTAs, 256 threads.  Per step: FULL 64x256 h tile loaded
// into smem in one deep-MLP burst (16 ldcv/thread), single sync, then all
// 192 mma run from resident smem (no intermediate syncs).
#define RWS 260                 // Ws stride (words): (4g+t) banks distinct
#define RAS 260                 // As stride (full 256-col tile)
#define RGS 100                 // Gs stride
#define SMEM_REC2 ((96 * RWS + 64 * RAS + 64 * RGS) * 4)   // 192000 B

__global__ __launch_bounds__(256) void recurrent_mma(
    const float* __restrict__ xg, const float* __restrict__ Whp,
    const float* __restrict__ bhp, const float* __restrict__ h0,
    const float* __restrict__ gamma, const float* __restrict__ beta,
    float* __restrict__ out_seq, float* __restrict__ final_h) {
    extern __shared__ uint32_t sm2[];
    uint32_t* Ws = sm2;                        // [96][RWS] tf32 Wh'
    uint32_t* As = sm2 + 96 * RWS;             // [64][RAS] tf32 full h tile
    float*    Gs = (float*)(sm2 + 96 * RWS + 64 * RAS);  // [64][RGS] h_gates

    const int tid = threadIdx.x;
    const int wid = tid >> 5, lane = tid & 31;
    const int g = lane >> 2, t = lane & 3;
    const int warp_m = wid & 1, warp_n = wid >> 1;
    const int n0 = blockIdx.x * 96;
    const int b0 = blockIdx.y * 64;
    const int grp = blockIdx.y;
    const int tx = tid & 15, ty = tid >> 4;
    const int c0 = 6 * tx;
    const int j0 = n0 / 3 + 2 * tx;

    // one-time: Wh' (gate-interleaved [n][k]) -> tf32 smem
    for (int idx = tid; idx < 96 * 256; idx += 256) {
        int n = idx >> 8, k = idx & 255;
        Ws[n * RWS + k] = cvt_tf32(Whp[(size_t)(n0 + n) * HH + k]);
    }

    float bias[6];
#pragma unroll
    for (int v = 0; v < 6; v++) bias[v] = bhp[n0 + c0 + v];

    float gm[4][2], bt[4][2];
#pragma unroll
    for (int i = 0; i < 4; i++) {
        int b = b0 + ty * 4 + i;
#pragma unroll
        for (int u = 0; u < 2; u++) {
            gm[i][u] = gamma[b * HH + j0 + u];
            bt[i][u] = beta [b * HH + j0 + u];
        }
    }

    {   // init hidden state
        int jb = n0 / 3;
        for (int idx = tid; idx < 64 * 32; idx += 256) {
            int rr = idx >> 5, cc = idx & 31;
            int off = (b0 + rr) * HH + jb + cc;
            g_hbuf[0][off] = h0[off];
        }
    }
    group_sync(grp);

    for (int step = 0; step < TT; step++) {
        const float* hcur = g_hbuf[step & 1];
        float* hnext = g_hbuf[(step + 1) & 1];

        // ---- load full h tile: 2 waves x 8 ldcv float4 per thread ----
#pragma unroll
        for (int w = 0; w < 2; w++) {
            float4 buf[8];
#pragma unroll
            for (int p = 0; p < 8; p++) {
                int idx = (w * 8 + p) * 256 + tid;
                int row = idx >> 6, kq = (idx & 63) * 4;
                buf[p] = __ldcv((const float4*)&hcur[(size_t)(b0 + row) * HH + kq]);
            }
#pragma unroll
            for (int p = 0; p < 8; p++) {
                int idx = (w * 8 + p) * 256 + tid;
                int row = idx >> 6, kq = (idx & 63) * 4;
                uint4 cv;
                cv.x = cvt_tf32(buf[p].x); cv.y = cvt_tf32(buf[p].y);
                cv.z = cvt_tf32(buf[p].z); cv.w = cvt_tf32(buf[p].w);
                *(uint4*)&As[row * RAS + kq] = cv;
            }
        }
        __syncthreads();

        // ---- GEMM: all k from resident smem, no further syncs ----
        float acc[2][3][4];
#pragma unroll
        for (int mt = 0; mt < 2; mt++)
#pragma unroll
            for (int nt = 0; nt < 3; nt++)
#pragma unroll
                for (int r = 0; r < 4; r++) acc[mt][nt][r] = 0.0f;

        for (int kc = 0; kc < HH; kc += 32) {
#pragma unroll
            for (int ks = 0; ks < 4; ks++) {
                const int k0 = kc + ks * 8;
                uint32_t a[2][4], b[3][2];
#pragma unroll
                for (int mt = 0; mt < 2; mt++) {
                    int r0 = warp_m * 32 + mt * 16;
                    a[mt][0] = As[(r0 + g) * RAS + k0 + t];
                    a[mt][1] = As[(r0 + g + 8) * RAS + k0 + t];
                    a[mt][2] = As[(r0 + g) * RAS + k0 + t + 4];
                    a[mt][3] = As[(r0 + g + 8) * RAS + k0 + t + 4];
                }
#pragma unroll
                for (int nt = 0; nt < 3; nt++) {
                    int cb = warp_n * 24 + nt * 8;
                    b[nt][0] = Ws[(cb + g) * RWS + k0 + t];
                    b[nt][1] = Ws[(cb + g) * RWS + k0 + t + 4];
                }
#pragma unroll
                for (int mt = 0; mt < 2; mt++)
#pragma unroll
                    for (int nt = 0; nt < 3; nt++)
                        mma_tf32(acc[mt][nt], a[mt], b[nt]);
            }
        }

        // stage h_gates to smem (decouple MMA fragment layout from gate math)
#pragma unroll
        for (int mt = 0; mt < 2; mt++) {
            int row = warp_m * 32 + mt * 16 + g;
#pragma unroll
            for (int nt = 0; nt < 3; nt++) {
                int col = warp_n * 24 + nt * 8 + 2 * t;
                *(float2*)&Gs[row * RGS + col] =
                    make_float2(acc[mt][nt][0], acc[mt][nt][1]);
                *(float2*)&Gs[(row + 8) * RGS + col] =
                    make_float2(acc[mt][nt][2], acc[mt][nt][3]);
            }
        }
        __syncthreads();

        // gates + FiLM + writes (proven mapping)
#pragma unroll
        for (int i = 0; i < 4; i++) {
            int b = b0 + ty * 4 + i;
            int rl = ty * 4 + i;
            const float* xgp = xg + ((size_t)step * BB + b) * G3 + n0 + c0;
            const float* gr = &Gs[rl * RGS + c0];
            float hv[2];
#pragma unroll
            for (int u = 0; u < 2; u++) {
                float z  = sigm_f(xgp[3 * u + 0] + gr[3 * u + 0] + bias[3 * u + 0]);
                float rr = sigm_f(xgp[3 * u + 1] + gr[3 * u + 1] + bias[3 * u + 1]);
                float nn = tanh_f(xgp[3 * u + 2] + rr * (gr[3 * u + 2] + bias[3 * u + 2]));
                float hp = __ldcv(&hcur[(size_t)b * HH + j0 + u]);
                float h  = nn + z * (hp - nn);
                hv[u] = fmaf(gm[i][u], h, bt[i][u]);
            }
            float2 hv2 = make_float2(hv[0], hv[1]);
            *(float2*)&hnext[(size_t)b * HH + j0] = hv2;
            *(float2*)&out_seq[((size_t)step * BB + b) * HH + j0] = hv2;
            if (step == TT - 1)
                *(float2*)&final_h[(size_t)b * HH + j0] = hv2;
        }
        group_sync(grp);
    }
}

// ---------------- host launcher -------------------------------------------
extern "C" void kernel_launch(void* const* d_in, const int* in_sizes, int n_in,
                              void* d_out, int out_size) {
    (void)in_sizes; (void)n_in; (void)out_size;
    const float* x      = (const float*)d_in[0];
    const float* init_s = (const float*)d_in[1];
    const float* gammas = (const float*)d_in[2];
    const float* betas  = (const float*)d_in[3];
    const float* Wx0 = (const float*)d_in[4];
    const float* bx0 = (const float*)d_in[5];
    const float* Wh0 = (const float*)d_in[6];
    const float* bh0 = (const float*)d_in[7];
    const float* Wx1 = (const float*)d_in[8];
    const float* bx1 = (const float*)d_in[9];
    const float* Wh1 = (const float*)d_in[10];
    const float* bh1 = (const float*)d_in[11];
    float* out = (float*)d_out;

    uint32_t *pWx0t, *pWx1t;
    float *pWh0p, *pWh1p, *pbx0p, *pbh0p, *pbx1p, *pbh1p, *pxg, *pout0;
    cudaGetSymbolAddress((void**)&pWx0t, g_Wx0t);
    cudaGetSymbolAddress((void**)&pWx1t, g_Wx1t);
    cudaGetSymbolAddress((void**)&pWh0p, g_Wh0p);
    cudaGetSymbolAddress((void**)&pWh1p, g_Wh1p);
    cudaGetSymbolAddress((void**)&pbx0p, g_bx0p);
    cudaGetSymbolAddress((void**)&pbh0p, g_bh0p);
    cudaGetSymbolAddress((void**)&pbx1p, g_bx1p);
    cudaGetSymbolAddress((void**)&pbh1p, g_bh1p);
    cudaGetSymbolAddress((void**)&pxg,   g_xg);
    cudaGetSymbolAddress((void**)&pout0, g_out0);

    cudaFuncSetAttribute(recurrent_mma,
                         cudaFuncAttributeMaxDynamicSharedMemorySize, SMEM_REC2);
    cudaFuncSetAttribute(xgates_mma,
                         cudaFuncAttributeMaxDynamicSharedMemorySize, XG_SMEM);

    const size_t out1_elems = (size_t)TT * BB * HH;

    reorder_kernel<<<768, 256>>>(Wx0, bx0, Wh0, bh0, Wx1, bx1, Wh1, bh1);

    // layer 0
    xgates_mma<<<dim3(6, 1024), 256, XG_SMEM>>>(x, pWx0t, pbx0p, pxg, DIN);
    recurrent_mma<<<dim3(8, 16), 256, SMEM_REC2>>>(
        pxg, pWh0p, pbh0p, init_s, gammas, betas,
        pout0, out + out1_elems);

    // layer 1
    xgates_mma<<<dim3(6, 1024), 256, XG_SMEM>>>(pout0, pWx1t, pbx1p, pxg, HH);
    recurrent_mma<<<dim3(8, 16), 256, SMEM_REC2>>>(
        pxg, pWh1p, pbh1p, init_s + BB * HH,
        gammas + (size_t)BB * HH, betas + (size_t)BB * HH,
        out, out + out1_elems + (size_t)BB * HH);
}